// round 6
// baseline (speedup 1.0000x reference)
#include <cuda_runtime.h>
#include <cuda_fp16.h>
#include <cstdint>

// Vanilla tanh RNN: h_t = tanh(x_t W_ih^T + b_ih + h_{t-1} W_hh^T + b_hh)
// B=4096, T=256, I=H=64. Output: [hT (B*H) | all h_t (B*T*H)] fp32.
//
// REGISTER-RESIDENT RECURRENCE: each warp owns 16 batch rows x all 64 cols.
// The m16n8k16 C-fragment of h_t IS the A-fragment of the next step's h-GEMM
// (pack c-pairs -> a-regs), so h never touches shared memory and there are
// ZERO barriers in the main loop. Per warp-step: 32 MMA (hW) + 32 MMA (xW for
// t+1) + 32 tanh.approx (1 MUFU each) + 16 STG.64. x flows through a 2-slot
// cp.async ring (only smem use). Weights register-resident. 128 blocks x 64
// threads -> 1 warp/SMSP (exclusive MUFU/LSU), 32 rows/block.

constexpr int Bsz = 4096;
constexpr int T   = 256;
constexpr int H   = 64;
constexpr int RPW = 16;            // rows per warp
constexpr int WPB = 2;             // warps per block
constexpr int ROWS_PER_BLOCK = RPW * WPB;
constexpr int NTHREADS = 32 * WPB;
constexpr int RSF = 68;            // x ring row stride (floats), degree-2 max

__device__ __forceinline__ uint32_t packh2(float a, float b) {
    __half2 h = __floats2half2_rn(a, b);
    return *reinterpret_cast<uint32_t*>(&h);
}

__device__ __forceinline__ void mma16(float* c, const uint32_t* a, const uint32_t* b) {
    asm volatile(
        "mma.sync.aligned.m16n8k16.row.col.f32.f16.f16.f32 "
        "{%0,%1,%2,%3}, {%4,%5,%6,%7}, {%8,%9}, {%0,%1,%2,%3};"
        : "+f"(c[0]), "+f"(c[1]), "+f"(c[2]), "+f"(c[3])
        : "r"(a[0]), "r"(a[1]), "r"(a[2]), "r"(a[3]), "r"(b[0]), "r"(b[1]));
}

__device__ __forceinline__ float tanh_mufu(float z) {
    float r;
    asm("tanh.approx.f32 %0, %1;" : "=f"(r) : "f"(z));
    return r;
}

__device__ __forceinline__ void cpasync16(uint32_t sdst, const void* gsrc) {
    asm volatile("cp.async.ca.shared.global [%0], [%1], 16;"
                 :: "r"(sdst), "l"(gsrc) : "memory");
}
__device__ __forceinline__ void cpcommit() {
    asm volatile("cp.async.commit_group;" ::: "memory");
}
__device__ __forceinline__ void cpwait1() {
    asm volatile("cp.async.wait_group 1;" ::: "memory");
}

__global__ void __launch_bounds__(NTHREADS, 1)
rnn_fused(const float* __restrict__ x, const float* __restrict__ h0,
          const float* __restrict__ Wih, const float* __restrict__ Whh,
          const float* __restrict__ bih, const float* __restrict__ bhh,
          float* __restrict__ dout)
{
    __shared__ __align__(16) float ring[2][WPB][RPW * RSF];

    const int lane = threadIdx.x & 31;
    const int warp = threadIdx.x >> 5;
    const int gid  = lane >> 2;      // 0..7
    const int tig  = lane & 3;       // 0..3

    const int wrow0 = blockIdx.x * ROWS_PER_BLOCK + warp * RPW;  // warp's row base
    const int row0  = wrow0 + gid;                               // this lane (and +8)

    // ---- weight B-fragments, register-resident: [nt][kt][2] ----
    uint32_t wih[8][4][2], whh[8][4][2];
    #pragma unroll
    for (int nt = 0; nt < 8; ++nt) {
        const int n = nt * 8 + gid;
        #pragma unroll
        for (int kt = 0; kt < 4; ++kt) {
            const int k = kt * 16 + 2 * tig;
            wih[nt][kt][0] = packh2(Wih[n * H + k],     Wih[n * H + k + 1]);
            wih[nt][kt][1] = packh2(Wih[n * H + k + 8], Wih[n * H + k + 9]);
            whh[nt][kt][0] = packh2(Whh[n * H + k],     Whh[n * H + k + 1]);
            whh[nt][kt][1] = packh2(Whh[n * H + k + 8], Whh[n * H + k + 9]);
        }
    }
    float bias[8][2];
    #pragma unroll
    for (int nt = 0; nt < 8; ++nt) {
        const int col = nt * 8 + 2 * tig;
        bias[nt][0] = bih[col]     + bhh[col];
        bias[nt][1] = bih[col + 1] + bhh[col + 1];
    }

    const float* xr0 = x + (size_t)row0 * T * H;        // row gid
    const float* xr1 = x + (size_t)(row0 + 8) * T * H;  // row gid+8

    // ---- hA = A-fragments of h_{t-1} (init from h0) ----
    uint32_t hA[4][4];
    #pragma unroll
    for (int kt = 0; kt < 4; ++kt) {
        const int k = kt * 16 + 2 * tig;
        float2 v0 = *(const float2*)(h0 + (size_t)row0 * H + k);
        float2 v1 = *(const float2*)(h0 + (size_t)(row0 + 8) * H + k);
        float2 v2 = *(const float2*)(h0 + (size_t)row0 * H + k + 8);
        float2 v3 = *(const float2*)(h0 + (size_t)(row0 + 8) * H + k + 8);
        hA[kt][0] = packh2(v0.x, v0.y);
        hA[kt][1] = packh2(v1.x, v1.y);
        hA[kt][2] = packh2(v2.x, v2.y);
        hA[kt][3] = packh2(v3.x, v3.y);
    }

    // ---- xA = A-fragments of x(1); xt temp = x(0) frags ----
    uint32_t xA[4][4];
    float acc[8][4];
    {
        uint32_t xt[4][4];
        #pragma unroll
        for (int kt = 0; kt < 4; ++kt) {
            const int k = kt * 16 + 2 * tig;
            float2 a0 = *(const float2*)(xr0 + 0 * H + k);
            float2 a1 = *(const float2*)(xr1 + 0 * H + k);
            float2 a2 = *(const float2*)(xr0 + 0 * H + k + 8);
            float2 a3 = *(const float2*)(xr1 + 0 * H + k + 8);
            xt[kt][0] = packh2(a0.x, a0.y);
            xt[kt][1] = packh2(a1.x, a1.y);
            xt[kt][2] = packh2(a2.x, a2.y);
            xt[kt][3] = packh2(a3.x, a3.y);
            float2 b0 = *(const float2*)(xr0 + 1 * H + k);
            float2 b1 = *(const float2*)(xr1 + 1 * H + k);
            float2 b2 = *(const float2*)(xr0 + 1 * H + k + 8);
            float2 b3 = *(const float2*)(xr1 + 1 * H + k + 8);
            xA[kt][0] = packh2(b0.x, b0.y);
            xA[kt][1] = packh2(b1.x, b1.y);
            xA[kt][2] = packh2(b2.x, b2.y);
            xA[kt][3] = packh2(b3.x, b3.y);
        }
        // acc = bias + x(0) @ W_ih^T
        #pragma unroll
        for (int nt = 0; nt < 8; ++nt) {
            acc[nt][0] = bias[nt][0]; acc[nt][1] = bias[nt][1];
            acc[nt][2] = bias[nt][0]; acc[nt][3] = bias[nt][1];
            #pragma unroll
            for (int kt = 0; kt < 4; ++kt)
                mma16(acc[nt], xt[kt], wih[nt][kt]);
        }
    }

    // ---- cp.async loader mapping: 8 chunks/thread cover 16 rows x 256B ----
    const int lrow  = lane >> 4;          // base row parity (0/1)
    const int lchk  = lane & 15;          // 16B chunk within row
    uint32_t rbase[2];
    rbase[0] = (uint32_t)__cvta_generic_to_shared(&ring[0][warp][0]);
    rbase[1] = (uint32_t)__cvta_generic_to_shared(&ring[1][warp][0]);
    const float* xgw = x + (size_t)wrow0 * T * H;  // warp row base

    // prologue: x(2) -> slot 0
    #pragma unroll
    for (int j = 0; j < 8; ++j) {
        const int r = j * 2 + lrow;
        cpasync16(rbase[0] + (r * RSF + lchk * 4) * 4,
                  xgw + (size_t)r * T * H + 2 * H + lchk * 4);
    }
    cpcommit();

    float* __restrict__ outp = dout + (size_t)Bsz * H;   // [hT | out]

    for (int t = 0; t < T; ++t) {
        // ---- prefetch x(t+3) -> slot (t+1)&1 (issued early, waited next step) ----
        {
            const int tf = (t + 3 < T) ? (t + 3) : (T - 1);
            const uint32_t rb = rbase[(t + 1) & 1];
            #pragma unroll
            for (int j = 0; j < 8; ++j) {
                const int r = j * 2 + lrow;
                cpasync16(rb + (r * RSF + lchk * 4) * 4,
                          xgw + (size_t)r * T * H + (size_t)tf * H + lchk * 4);
            }
            cpcommit();
        }

        // ---- h-GEMM: acc += h_{t-1} @ W_hh^T (8 independent 4-chains) ----
        #pragma unroll
        for (int nt = 0; nt < 8; ++nt)
            #pragma unroll
            for (int kt = 0; kt < 4; ++kt)
                mma16(acc[nt], hA[kt], whh[nt][kt]);

        // ---- tanh, out stores, repack into hA, reinit acc ----
        #pragma unroll
        for (int nt = 0; nt < 8; ++nt) {
            const float v0 = tanh_mufu(acc[nt][0]);
            const float v1 = tanh_mufu(acc[nt][1]);
            const float v2 = tanh_mufu(acc[nt][2]);
            const float v3 = tanh_mufu(acc[nt][3]);
            const int col = nt * 8 + 2 * tig;
            *(float2*)(outp + ((size_t)row0 * T + t) * H + col) = make_float2(v0, v1);
            *(float2*)(outp + ((size_t)(row0 + 8) * T + t) * H + col) = make_float2(v2, v3);
            if (t == T - 1) {   // final hidden state
                *(float2*)(dout + (size_t)row0 * H + col) = make_float2(v0, v1);
                *(float2*)(dout + (size_t)(row0 + 8) * H + col) = make_float2(v2, v3);
            }
            // C-frag -> A-frag: n-tile nt feeds k-tile nt/2, regs (nt&1)*2 +{0,1}
            hA[nt >> 1][(nt & 1) * 2 + 0] = packh2(v0, v1);
            hA[nt >> 1][(nt & 1) * 2 + 1] = packh2(v2, v3);
            acc[nt][0] = bias[nt][0]; acc[nt][1] = bias[nt][1];
            acc[nt][2] = bias[nt][0]; acc[nt][3] = bias[nt][1];
        }

        // ---- x-GEMM (off recurrence chain): acc += x(t+1) @ W_ih^T ----
        #pragma unroll
        for (int nt = 0; nt < 8; ++nt)
            #pragma unroll
            for (int kt = 0; kt < 4; ++kt)
                mma16(acc[nt], xA[kt], wih[nt][kt]);

        // ---- pack x(t+2) from ring slot t&1 into xA ----
        cpwait1();   // drains x(t+2); x(t+3) may still fly
        {
            const float* rp = &ring[t & 1][warp][0];
            #pragma unroll
            for (int kt = 0; kt < 4; ++kt) {
                const int k = kt * 16 + 2 * tig;
                float2 a0 = *(const float2*)(rp + gid * RSF + k);
                float2 a1 = *(const float2*)(rp + (gid + 8) * RSF + k);
                float2 a2 = *(const float2*)(rp + gid * RSF + k + 8);
                float2 a3 = *(const float2*)(rp + (gid + 8) * RSF + k + 8);
                xA[kt][0] = packh2(a0.x, a0.y);
                xA[kt][1] = packh2(a1.x, a1.y);
                xA[kt][2] = packh2(a2.x, a2.y);
                xA[kt][3] = packh2(a3.x, a3.y);
            }
        }
    }
}

extern "C" void kernel_launch(void* const* d_in, const int* in_sizes, int n_in,
                              void* d_out, int out_size) {
    const float* x   = (const float*)d_in[0];
    const float* h0  = (const float*)d_in[1];
    const float* Wih = (const float*)d_in[2];
    const float* Whh = (const float*)d_in[3];
    const float* bih = (const float*)d_in[4];
    const float* bhh = (const float*)d_in[5];
    (void)in_sizes; (void)n_in; (void)out_size;

    rnn_fused<<<Bsz / ROWS_PER_BLOCK, NTHREADS>>>(x, h0, Wih, Whh, bih, bhh,
                                                  (float*)d_out);
}

// round 7
// speedup vs baseline: 1.3192x; 1.3192x over previous
#include <cuda_runtime.h>
#include <cuda.h>
#include <cuda_fp16.h>
#include <cstdint>

// Vanilla tanh RNN: h_t = tanh(x_t W_ih^T + b_ih + h_{t-1} W_hh^T + b_hh)
// B=4096, T=256, I=H=64. Output: [hT (B*H) | all h_t (B*T*H)] fp32.
//
// DRAM-pattern-optimized version: the recurrence is register-resident per
// warp (C-fragment of h_t == A-fragment of next h-GEMM), and ALL bulk I/O
// goes through TMA in 8-step chunks: x loaded 32KB at a time (2KB contiguous
// per batch row) double-buffered + prefetched one chunk ahead; out staged in
// swizzled smem and written 32KB at a time. 256 blocks x 32 threads, 16 rows
// per block, zero barriers (single warp).

constexpr int Bsz = 4096, T = 256, H = 64;
constexpr int RPB = 16;              // batch rows per block
constexpr int GRID = Bsz / RPB;      // 256
constexpr int CH  = 8;               // timesteps per chunk
constexpr int NCH = T / CH;          // 32
constexpr int XB  = 16384;           // bytes per half tile (128 rows x 128B)
constexpr int SM_X = 0;              // x tiles: [2 buf][2 half] = 64KB
constexpr int SM_O = 65536;          // out tile: [2 half] = 32KB
constexpr int SM_MB = 98304;         // mbarriers
constexpr int SMEM_TOTAL = 98432;

__device__ __forceinline__ uint32_t packh2(float a, float b) {
    __half2 h = __floats2half2_rn(a, b);
    return *reinterpret_cast<uint32_t*>(&h);
}

__device__ __forceinline__ void mma16(float* c, const uint32_t* a, const uint32_t* b) {
    asm volatile(
        "mma.sync.aligned.m16n8k16.row.col.f32.f16.f16.f32 "
        "{%0,%1,%2,%3}, {%4,%5,%6,%7}, {%8,%9}, {%0,%1,%2,%3};"
        : "+f"(c[0]), "+f"(c[1]), "+f"(c[2]), "+f"(c[3])
        : "r"(a[0]), "r"(a[1]), "r"(a[2]), "r"(a[3]), "r"(b[0]), "r"(b[1]));
}

__device__ __forceinline__ float tanh_mufu(float z) {
    float r;
    asm("tanh.approx.f32 %0, %1;" : "=f"(r) : "f"(z));
    return r;
}

__device__ __forceinline__ void tma_load3d(uint32_t sdst, const CUtensorMap* m,
                                           int cx, int cy, int cz, uint32_t mbar) {
    asm volatile(
        "cp.async.bulk.tensor.3d.shared::cta.global.tile.mbarrier::complete_tx::bytes "
        "[%0], [%1, {%2, %3, %4}], [%5];"
        :: "r"(sdst), "l"(m), "r"(cx), "r"(cy), "r"(cz), "r"(mbar) : "memory");
}

__device__ __forceinline__ void tma_store3d(const CUtensorMap* m,
                                            int cx, int cy, int cz, uint32_t ssrc) {
    asm volatile(
        "cp.async.bulk.tensor.3d.global.shared::cta.tile.bulk_group "
        "[%0, {%1, %2, %3}], [%4];"
        :: "l"(m), "r"(cx), "r"(cy), "r"(cz), "r"(ssrc) : "memory");
}

__device__ __forceinline__ void mbar_wait(uint32_t mbar, int parity) {
    asm volatile(
        "{\n\t.reg .pred P;\n\t"
        "W%=:\n\t"
        "mbarrier.try_wait.parity.acquire.cta.shared::cta.b64 P, [%0], %1, 0x989680;\n\t"
        "@!P bra W%=;\n\t}"
        :: "r"(mbar), "r"(parity) : "memory");
}

__global__ void __launch_bounds__(32, 1)
rnn_fused(const __grid_constant__ CUtensorMap xmap,
          const __grid_constant__ CUtensorMap omap,
          const float* __restrict__ h0,
          const float* __restrict__ Wih, const float* __restrict__ Whh,
          const float* __restrict__ bih, const float* __restrict__ bhh,
          float* __restrict__ dout)
{
    extern __shared__ __align__(1024) char smem[];
    const uint32_t sb  = (uint32_t)__cvta_generic_to_shared(smem);
    const uint32_t mb0 = sb + SM_MB, mb1 = sb + SM_MB + 8;

    const int lane = threadIdx.x;
    const int gid  = lane >> 2;   // 0..7
    const int tig  = lane & 3;    // 0..3
    const int b0   = blockIdx.x * RPB;
    const int row0 = b0 + gid;
    const uint32_t key = (uint32_t)gid << 4;   // SW128 xor for rows gid, gid+8

    // ---- kick off TMA: mbar init + chunks 0,1 (before weight LDGs) ----
    if (lane == 0) {
        asm volatile("mbarrier.init.shared.b64 [%0], 1;" :: "r"(mb0));
        asm volatile("mbarrier.init.shared.b64 [%0], 1;" :: "r"(mb1));
        asm volatile("fence.proxy.async.shared::cta;" ::: "memory");
        asm volatile("mbarrier.arrive.expect_tx.shared.b64 _, [%0], %1;"
                     :: "r"(mb0), "r"(2 * XB));
        tma_load3d(sb + SM_X + 0,      &xmap, 0,  b0, 0, mb0);
        tma_load3d(sb + SM_X + XB,     &xmap, 32, b0, 0, mb0);
        asm volatile("mbarrier.arrive.expect_tx.shared.b64 _, [%0], %1;"
                     :: "r"(mb1), "r"(2 * XB));
        tma_load3d(sb + SM_X + 32768,      &xmap, 0,  b0, CH, mb1);
        tma_load3d(sb + SM_X + 32768 + XB, &xmap, 32, b0, CH, mb1);
    }

    // ---- weight B-fragments (fp16, register resident): [nt][kt][2] ----
    uint32_t wih[8][4][2], whh[8][4][2];
    #pragma unroll
    for (int nt = 0; nt < 8; ++nt) {
        const int n = nt * 8 + gid;
        #pragma unroll
        for (int kt = 0; kt < 4; ++kt) {
            const int k = kt * 16 + 2 * tig;
            wih[nt][kt][0] = packh2(Wih[n * H + k],     Wih[n * H + k + 1]);
            wih[nt][kt][1] = packh2(Wih[n * H + k + 8], Wih[n * H + k + 9]);
            whh[nt][kt][0] = packh2(Whh[n * H + k],     Whh[n * H + k + 1]);
            whh[nt][kt][1] = packh2(Whh[n * H + k + 8], Whh[n * H + k + 9]);
        }
    }
    float bias[8][2];
    #pragma unroll
    for (int nt = 0; nt < 8; ++nt) {
        const int col = nt * 8 + 2 * tig;
        bias[nt][0] = bih[col]     + bhh[col];
        bias[nt][1] = bih[col + 1] + bhh[col + 1];
    }

    // ---- hA = A-fragments of h (init h0) ----
    uint32_t hA[4][4];
    #pragma unroll
    for (int kt = 0; kt < 4; ++kt) {
        const int k = kt * 16 + 2 * tig;
        float2 v0 = *(const float2*)(h0 + (size_t)row0 * H + k);
        float2 v1 = *(const float2*)(h0 + (size_t)(row0 + 8) * H + k);
        float2 v2 = *(const float2*)(h0 + (size_t)row0 * H + k + 8);
        float2 v3 = *(const float2*)(h0 + (size_t)(row0 + 8) * H + k + 8);
        hA[kt][0] = packh2(v0.x, v0.y);
        hA[kt][1] = packh2(v1.x, v1.y);
        hA[kt][2] = packh2(v2.x, v2.y);
        hA[kt][3] = packh2(v3.x, v3.y);
    }

    // xA pack from swizzled x tile: buf in {0,1}, tt in [0,8)
    uint32_t xA[4][4];
    auto pack_xA = [&](int buf, int tt) {
        const char* tb = smem + SM_X + buf * 32768;
        #pragma unroll
        for (int kt = 0; kt < 4; ++kt) {
            const int half = kt >> 1;
            const uint32_t c4 = (uint32_t)(((kt & 1) * 16 + 2 * tig) * 4);
            const char* base = tb + half * XB + tt * 2048;
            const uint32_t o0 = (uint32_t)(gid * 128) + c4;
            float2 a0 = *(const float2*)(base + ((o0)          ^ key));
            float2 a1 = *(const float2*)(base + ((o0 + 1024)   ^ key));
            float2 a2 = *(const float2*)(base + ((o0 + 32)     ^ key));
            float2 a3 = *(const float2*)(base + ((o0 + 1056)   ^ key));
            xA[kt][0] = packh2(a0.x, a0.y);
            xA[kt][1] = packh2(a1.x, a1.y);
            xA[kt][2] = packh2(a2.x, a2.y);
            xA[kt][3] = packh2(a3.x, a3.y);
        }
    };

    // ---- prologue: wait x chunk0, acc = bias + x(0) @ W_ih^T ----
    mbar_wait(mb0, 0);
    int ph0 = 1, ph1 = 0;
    pack_xA(0, 0);
    float acc[8][4];
    #pragma unroll
    for (int nt = 0; nt < 8; ++nt) {
        acc[nt][0] = bias[nt][0]; acc[nt][1] = bias[nt][1];
        acc[nt][2] = bias[nt][0]; acc[nt][3] = bias[nt][1];
        #pragma unroll
        for (int kt = 0; kt < 4; ++kt)
            mma16(acc[nt], xA[kt], wih[nt][kt]);
    }

    for (int c = 0; c < NCH; ++c) {
        const int cur = c & 1;

        #pragma unroll
        for (int tt = 0; tt < CH; ++tt) {
            const int t = c * CH + tt;

            // ---- h-GEMM: acc += h_{t-1} @ W_hh^T ----
            #pragma unroll
            for (int nt = 0; nt < 8; ++nt)
                #pragma unroll
                for (int kt = 0; kt < 4; ++kt)
                    mma16(acc[nt], hA[kt], whh[nt][kt]);

            // ---- tanh, STS to out tile (swizzled), repack hA, reinit acc ----
            #pragma unroll
            for (int nt = 0; nt < 8; ++nt) {
                const float v0 = tanh_mufu(acc[nt][0]);
                const float v1 = tanh_mufu(acc[nt][1]);
                const float v2 = tanh_mufu(acc[nt][2]);
                const float v3 = tanh_mufu(acc[nt][3]);
                char* ob = smem + SM_O + (nt >> 2) * XB + tt * 2048;
                const uint32_t o0 = (uint32_t)(gid * 128 + ((nt & 3) * 8 + 2 * tig) * 4);
                *(float2*)(ob + ((o0)        ^ key)) = make_float2(v0, v1);
                *(float2*)(ob + ((o0 + 1024) ^ key)) = make_float2(v2, v3);
                hA[nt >> 1][(nt & 1) * 2 + 0] = packh2(v0, v1);
                hA[nt >> 1][(nt & 1) * 2 + 1] = packh2(v2, v3);
                if (t == T - 1) {   // final hidden state, direct STG
                    const int col = nt * 8 + 2 * tig;
                    *(float2*)(dout + (size_t)row0 * H + col) = make_float2(v0, v1);
                    *(float2*)(dout + (size_t)(row0 + 8) * H + col) = make_float2(v2, v3);
                }
                acc[nt][0] = bias[nt][0]; acc[nt][1] = bias[nt][1];
                acc[nt][2] = bias[nt][0]; acc[nt][3] = bias[nt][1];
            }

            // ---- x-GEMM for t+1 (off the recurrence chain) ----
            if (t < T - 1) {
                if (tt == CH - 1) {
                    if (cur == 0) { mbar_wait(mb1, ph1); ph1 ^= 1; }
                    else          { mbar_wait(mb0, ph0); ph0 ^= 1; }
                    pack_xA(cur ^ 1, 0);
                } else {
                    pack_xA(cur, tt + 1);
                }
                #pragma unroll
                for (int nt = 0; nt < 8; ++nt)
                    #pragma unroll
                    for (int kt = 0; kt < 4; ++kt)
                        mma16(acc[nt], xA[kt], wih[nt][kt]);
            }
        }

        // ---- chunk epilogue: TMA store out, refill consumed x buffer ----
        __syncwarp();
        if (lane == 0) {
            asm volatile("fence.proxy.async.shared::cta;" ::: "memory");
            tma_store3d(&omap, 0,  b0, c * CH, sb + SM_O);
            tma_store3d(&omap, 32, b0, c * CH, sb + SM_O + XB);
            asm volatile("cp.async.bulk.commit_group;" ::: "memory");
            if (c + 2 < NCH) {
                const uint32_t mb = cur ? mb1 : mb0;
                asm volatile("mbarrier.arrive.expect_tx.shared.b64 _, [%0], %1;"
                             :: "r"(mb), "r"(2 * XB));
                tma_load3d(sb + SM_X + cur * 32768,      &xmap, 0,  b0, (c + 2) * CH, mb);
                tma_load3d(sb + SM_X + cur * 32768 + XB, &xmap, 32, b0, (c + 2) * CH, mb);
            }
            // out tile reusable once the store has READ smem
            asm volatile("cp.async.bulk.wait_group.read 0;" ::: "memory");
        }
        __syncwarp();
    }

    if (lane == 0)
        asm volatile("cp.async.bulk.wait_group 0;" ::: "memory");
}

typedef CUresult (*tmap_encode_fn)(
    CUtensorMap*, CUtensorMapDataType, cuuint32_t, void*,
    const cuuint64_t*, const cuuint64_t*, const cuuint32_t*, const cuuint32_t*,
    CUtensorMapInterleave, CUtensorMapSwizzle, CUtensorMapL2promotion,
    CUtensorMapFloatOOBfill);

extern "C" void kernel_launch(void* const* d_in, const int* in_sizes, int n_in,
                              void* d_out, int out_size) {
    const float* x   = (const float*)d_in[0];
    const float* h0  = (const float*)d_in[1];
    const float* Wih = (const float*)d_in[2];
    const float* Whh = (const float*)d_in[3];
    const float* bih = (const float*)d_in[4];
    const float* bhh = (const float*)d_in[5];
    float* dout = (float*)d_out;
    (void)in_sizes; (void)n_in; (void)out_size;

    // Tensor-map encoder via runtime entry point (no -lcuda needed).
    void* fn = nullptr;
    cudaDriverEntryPointQueryResult qr;
    cudaGetDriverEntryPointByVersion("cuTensorMapEncodeTiled", &fn, 12000,
                                     cudaEnableDefault, &qr);
    tmap_encode_fn enc = (tmap_encode_fn)fn;

    // Both x and out are [B, T, 64] fp32 row-major.
    // dims: (h=64, b=4096, t=256); strides: b->64KB, t->256B; box (32, 16, 8).
    cuuint64_t gdim[3] = {64, (cuuint64_t)Bsz, (cuuint64_t)T};
    cuuint64_t gstr[2] = {(cuuint64_t)T * H * sizeof(float),
                          (cuuint64_t)H * sizeof(float)};
    cuuint32_t box[3]  = {32, RPB, CH};
    cuuint32_t estr[3] = {1, 1, 1};

    CUtensorMap xmap, omap;
    enc(&xmap, CU_TENSOR_MAP_DATA_TYPE_FLOAT32, 3, (void*)x,
        gdim, gstr, box, estr, CU_TENSOR_MAP_INTERLEAVE_NONE,
        CU_TENSOR_MAP_SWIZZLE_128B, CU_TENSOR_MAP_L2_PROMOTION_L2_128B,
        CU_TENSOR_MAP_FLOAT_OOB_FILL_NONE);
    enc(&omap, CU_TENSOR_MAP_DATA_TYPE_FLOAT32, 3, (void*)(dout + (size_t)Bsz * H),
        gdim, gstr, box, estr, CU_TENSOR_MAP_INTERLEAVE_NONE,
        CU_TENSOR_MAP_SWIZZLE_128B, CU_TENSOR_MAP_L2_PROMOTION_L2_128B,
        CU_TENSOR_MAP_FLOAT_OOB_FILL_NONE);

    cudaFuncSetAttribute(rnn_fused, cudaFuncAttributeMaxDynamicSharedMemorySize,
                         SMEM_TOTAL);
    rnn_fused<<<GRID, 32, SMEM_TOTAL>>>(xmap, omap, h0, Wih, Whh, bih, bhh, dout);
}